// round 15
// baseline (speedup 1.0000x reference)
#include <cuda_runtime.h>
#include <cuda_fp16.h>
#include <cstdint>
#include <math.h>

// ---------------- problem constants ----------------
constexpr int NB   = 32;
constexpr int NC   = 768;
constexpr int CIN0 = 80;
constexpr int CIN1P = 96;
constexpr int T0   = 1024;
constexpr int T1   = 1022;
constexpr int T2   = 511;
constexpr int ND   = 64;
constexpr int NM   = 512;
constexpr int NQ   = NB * T2;
constexpr int NQE  = NQ * ND;
constexpr float BN_EPS = 1e-5f;
constexpr float WSCALE = 1024.0f;

constexpr int KK1P = CIN1P * 3;    // 288
constexpr int KK2  = NC * 3;       // 2304
constexpr int KK3  = NC * 4;       // 3072

// swizzled 64B rows, 3 stages
constexpr int ROWB   = 64;
constexpr int PL     = 128 * ROWB;            // 8192 per plane
constexpr int STG    = 4 * PL;                // 32768 (Ah, Al, Bh, Bl)
constexpr int SMEM2  = 3 * STG;               // 98304

// ---------------- scratch ----------------
__device__ __align__(16) __half g_m_h[NB * T0 * CIN1P];
__device__ __align__(16) __half g_m_l[NB * T0 * CIN1P];
__device__ __align__(16) __half g_w1h[NC * KK1P], g_w1l[NC * KK1P];
__device__ __align__(16) __half g_pA_h[NB * T1 * NC];
__device__ __align__(16) __half g_pA_l[NB * T1 * NC];
__device__ __align__(16) __half g_pB_h[NB * T1 * NC];
__device__ __align__(16) __half g_pB_l[NB * T1 * NC];
__device__ __align__(16) __half g_w2h[NC * KK2], g_w2l[NC * KK2];
__device__ __align__(16) __half g_w3h[NC * KK3], g_w3l[NC * KK3];
__device__ __align__(16) __half g_w4h[NC * KK2], g_w4l[NC * KK2];
__device__ __align__(16) __half g_w5h[NC * KK2], g_w5l[NC * KK2];
__device__ float g_z[NQE];
__device__ float g_dist[NQ * NM];
__device__ float g_bnInv[5 * NC];
__device__ float g_bnBeta[5 * NC];
__device__ float g_e2[NM];
__device__ int   g_counts[NM];
__device__ float g_loss[1];

// ---------------- helpers ----------------
__device__ __forceinline__ void splitstore(float v, __half* ph, __half* pl) {
    __half h = __float2half_rn(v);
    *ph = h;
    *pl = __float2half_rn(v - __half2float(h));
}

__device__ __forceinline__ void mma16816(float* c, const uint32_t* a, const uint32_t* b) {
    asm volatile(
        "mma.sync.aligned.m16n8k16.row.col.f32.f16.f16.f32 "
        "{%0,%1,%2,%3}, {%4,%5,%6,%7}, {%8,%9}, {%0,%1,%2,%3};"
        : "+f"(c[0]), "+f"(c[1]), "+f"(c[2]), "+f"(c[3])
        : "r"(a[0]), "r"(a[1]), "r"(a[2]), "r"(a[3]), "r"(b[0]), "r"(b[1]));
}

__device__ __forceinline__ void cpa16(uint32_t d, const void* s, int sz) {
    asm volatile("cp.async.cg.shared.global [%0], [%1], 16, %2;"
                 :: "r"(d), "l"(s), "r"(sz) : "memory");
}
__device__ __forceinline__ void cp_commit() {
    asm volatile("cp.async.commit_group;" ::: "memory");
}
__device__ __forceinline__ void cp_wait1() {
    asm volatile("cp.async.wait_group 1;" ::: "memory");
}
__device__ __forceinline__ void cp_wait0() {
    asm volatile("cp.async.wait_group 0;" ::: "memory");
}

__device__ __forceinline__ void ldsm_x4(uint32_t* r, uint32_t a) {
    asm volatile("ldmatrix.sync.aligned.m8n8.x4.shared.b16 {%0,%1,%2,%3}, [%4];"
                 : "=r"(r[0]), "=r"(r[1]), "=r"(r[2]), "=r"(r[3]) : "r"(a));
}

// ---------------- prep kernels ----------------
__global__ void prep_k(const float* __restrict__ g, const float* __restrict__ b,
                       const float* __restrict__ m, const float* __restrict__ v,
                       const float* __restrict__ emb) {
    int i = blockIdx.x * blockDim.x + threadIdx.x;
    if (i < 5 * NC) {
        float inv = g[i] * rsqrtf(v[i] + BN_EPS);
        g_bnInv[i]  = inv / WSCALE;
        g_bnBeta[i] = b[i] - m[i] * inv;
    }
    if (i < NM) {
        g_counts[i] = 0;
        float s = 0.f;
        #pragma unroll
        for (int d = 0; d < ND; d++) { float t = emb[i * ND + d]; s += t * t; }
        g_e2[i] = s;
    }
    if (i == NM) g_loss[0] = 0.f;
}

__global__ void packall_k(const float* __restrict__ w1, const float* __restrict__ w2,
                          const float* __restrict__ w3, const float* __restrict__ w4,
                          const float* __restrict__ w5, const float* __restrict__ mels) {
    int i = blockIdx.x * blockDim.x + threadIdx.x;
    if (i < NC * KK1P) {
        int mm = i / KK1P, k = i - mm * KK1P;
        int kp = k / CIN1P, ci = k - kp * CIN1P;
        float v = (ci < CIN0) ? w1[((size_t)mm * CIN0 + ci) * 3 + kp] * WSCALE : 0.f;
        splitstore(v, &g_w1h[i], &g_w1l[i]);
        return;
    }
    i -= NC * KK1P;
    if (i < NC * KK2) {
        int mm = i / KK2, k = i - mm * KK2;
        int kp = k / NC, ci = k - kp * NC;
        float v = w2[((size_t)mm * NC + ci) * 3 + kp] * WSCALE;
        splitstore(v, &g_w2h[i], &g_w2l[i]);
        return;
    }
    i -= NC * KK2;
    if (i < NC * KK3) {
        int mm = i / KK3, k = i - mm * KK3;
        int kp = k / NC, ci = k - kp * NC;
        float v = w3[((size_t)mm * NC + ci) * 4 + kp] * WSCALE;
        splitstore(v, &g_w3h[i], &g_w3l[i]);
        return;
    }
    i -= NC * KK3;
    if (i < NC * KK2) {
        int mm = i / KK2, k = i - mm * KK2;
        int kp = k / NC, ci = k - kp * NC;
        float v = w4[((size_t)mm * NC + ci) * 3 + kp] * WSCALE;
        splitstore(v, &g_w4h[i], &g_w4l[i]);
        return;
    }
    i -= NC * KK2;
    if (i < NC * KK2) {
        int mm = i / KK2, k = i - mm * KK2;
        int kp = k / NC, ci = k - kp * NC;
        float v = w5[((size_t)mm * NC + ci) * 3 + kp] * WSCALE;
        splitstore(v, &g_w5h[i], &g_w5l[i]);
        return;
    }
    i -= NC * KK2;
    if (i < NB * T0 * CIN1P) {
        int bb = i / (T0 * CIN1P), r = i - bb * T0 * CIN1P;
        int t = r / CIN1P, ci = r - t * CIN1P;
        float v = (ci < CIN0) ? mels[((size_t)bb * CIN0 + ci) * T0 + t] : 0.f;
        splitstore(v, &g_m_h[i], &g_m_l[i]);
    }
}
constexpr int PACKALL_N = NC * KK1P + 3 * (NC * KK2) + NC * KK3 + NB * T0 * CIN1P;

// ===== conv: 128 threads, 4 warps (2x2), warp tile 64x64, 3-stage pipeline =====
template<int CIN, int KW, int STRIDE, int PAD, int TIN, int TOUT>
__device__ __forceinline__
void conv_cl_body(const __half* __restrict__ xh, const __half* __restrict__ xl,
                  const __half* __restrict__ wh, const __half* __restrict__ wl,
                  const float* __restrict__ inv, const float* __restrict__ bet,
                  __half* __restrict__ oh, __half* __restrict__ ol)
{
    constexpr int KK  = CIN * KW;
    constexpr int NS  = KK / 32;
    constexpr int NCOLS = NB * TOUT;

    extern __shared__ char smem[];
    const uint32_t sbase = (uint32_t)__cvta_generic_to_shared(smem);

    const int tid  = threadIdx.x;
    const int lane = tid & 31;
    const int warp = tid >> 5;        // 0..3
    const int gid  = lane >> 2;
    const int tig  = lane & 3;
    const int mw   = warp >> 1;       // 0..1
    const int nw   = warp & 1;        // 0..1
    const int m0 = blockIdx.y * 128;
    const int n0 = blockIdx.x * 128;

    // cp.async task: 128 threads cover 256 rows (A 0..127, B 0..127), 2 rows each.
    // thread t: rows t (first) and t+128... map: isA = tid<64 handles A rows tid, tid+64;
    // tid>=64 handles B rows (tid-64), (tid-64)+64.
    const bool isA  = tid < 64;
    const int r0a   = isA ? tid : (tid - 64);
    const int rows_[2] = { r0a, r0a + 64 };

    // B-row descriptors (for tid>=64)
    int  nbB[2], tB[2];
    bool cvB[2];
    #pragma unroll
    for (int j = 0; j < 2; j++) {
        int ncol = n0 + rows_[j];
        cvB[j] = (!isA) && (ncol < NCOLS);
        int nb = cvB[j] ? (ncol / TOUT) : 0;
        nbB[j] = nb;
        tB[j]  = cvB[j] ? (ncol - nb * TOUT) : 0;
    }

    float acc[4][8][4];
    #pragma unroll
    for (int a = 0; a < 4; a++)
        #pragma unroll
        for (int b = 0; b < 8; b++)
            #pragma unroll
            for (int c = 0; c < 4; c++) acc[a][b][c] = 0.f;

    // precomputed ldsm offsets (stage-invariant)
    uint32_t offA[2][4], offB[2][4];
    {
        const int cbA = lane >> 4;
        #pragma unroll
        for (int mi = 0; mi < 4; mi++) {
            int r = mw * 64 + mi * 16 + (lane & 15);
            int sw = (r >> 1) & 3;
            #pragma unroll
            for (int kh = 0; kh < 2; kh++)
                offA[kh][mi] = (uint32_t)(r * ROWB + ((((kh * 2 + cbA) ^ sw) & 3) << 4));
        }
        const int cbB = (lane >> 3) & 1;
        const int gB  = (lane >> 4) & 1;
        #pragma unroll
        for (int q = 0; q < 4; q++) {
            int r = nw * 64 + (q * 2 + gB) * 8 + (lane & 7);
            int sw = (r >> 1) & 3;
            #pragma unroll
            for (int kh = 0; kh < 2; kh++)
                offB[kh][q] = (uint32_t)(r * ROWB + ((((kh * 2 + cbB) ^ sw) & 3) << 4));
        }
    }

    auto ISSUE = [&](int s) {
        const uint32_t stb = sbase + (uint32_t)(s % 3) * STG;
        const int kt = s * 32;
        if (isA) {
            #pragma unroll
            for (int j = 0; j < 2; j++) {
                int r = rows_[j];
                const __half* sh = wh + (size_t)(m0 + r) * KK + kt;
                const __half* sl = wl + (size_t)(m0 + r) * KK + kt;
                int sw = (r >> 1) & 3;
                uint32_t db = stb + (uint32_t)r * ROWB;
                #pragma unroll
                for (int c = 0; c < 4; c++) {
                    uint32_t d = db + (uint32_t)(((c ^ sw) & 3) << 4);
                    cpa16(d,      sh + c * 8, 16);
                    cpa16(d + PL, sl + c * 8, 16);
                }
            }
        } else {
            int kp  = kt / CIN;
            int ci0 = kt - kp * CIN;
            #pragma unroll
            for (int j = 0; j < 2; j++) {
                int r = rows_[j];
                int tin = tB[j] * STRIDE + kp - PAD;
                bool ok = cvB[j] && tin >= 0 && tin < TIN;
                int tin_c = ok ? tin : 0;
                const __half* sh = xh + ((size_t)nbB[j] * TIN + tin_c) * CIN + ci0;
                const __half* sl = xl + ((size_t)nbB[j] * TIN + tin_c) * CIN + ci0;
                int sz = ok ? 16 : 0;
                int sw = (r >> 1) & 3;
                uint32_t db = stb + 2u * PL + (uint32_t)r * ROWB;
                #pragma unroll
                for (int c = 0; c < 4; c++) {
                    uint32_t d = db + (uint32_t)(((c ^ sw) & 3) << 4);
                    cpa16(d,      sh + c * 8, sz);
                    cpa16(d + PL, sl + c * 8, sz);
                }
            }
        }
        cp_commit();
    };

    auto COMPUTE = [&](int st) {
        const uint32_t pA = sbase + (uint32_t)st * STG;
        const uint32_t pB = pA + 2u * PL;
        #pragma unroll
        for (int kh = 0; kh < 2; kh++) {
            uint32_t bH[8][2], bL[8][2];
            #pragma unroll
            for (int q = 0; q < 4; q++) {
                uint32_t t[4];
                ldsm_x4(t, pB + offB[kh][q]);
                bH[q*2][0] = t[0]; bH[q*2][1] = t[1]; bH[q*2+1][0] = t[2]; bH[q*2+1][1] = t[3];
                ldsm_x4(t, pB + PL + offB[kh][q]);
                bL[q*2][0] = t[0]; bL[q*2][1] = t[1]; bL[q*2+1][0] = t[2]; bL[q*2+1][1] = t[3];
            }
            #pragma unroll
            for (int mi = 0; mi < 4; mi++) {
                uint32_t aH[4], aL[4];
                ldsm_x4(aH, pA + offA[kh][mi]);
                ldsm_x4(aL, pA + PL + offA[kh][mi]);
                // term-major: same-acc reuse 8 MMAs apart
                #pragma unroll
                for (int ni = 0; ni < 8; ni++) mma16816(acc[mi][ni], aH, bH[ni]);
                #pragma unroll
                for (int ni = 0; ni < 8; ni++) mma16816(acc[mi][ni], aH, bL[ni]);
                #pragma unroll
                for (int ni = 0; ni < 8; ni++) mma16816(acc[mi][ni], aL, bH[ni]);
            }
        }
    };

    ISSUE(0);
    ISSUE(1);
    for (int s = 0; s < NS; s++) {
        if (s + 1 < NS) cp_wait1(); else cp_wait0();
        __syncthreads();
        if (s + 2 < NS) ISSUE(s + 2);
        COMPUTE(s % 3);
    }

    // epilogue: BN+ReLU -> channel-last hi/lo planes
    #pragma unroll
    for (int mi = 0; mi < 4; mi++) {
        int r1 = m0 + mw * 64 + mi * 16 + gid;
        int r2 = r1 + 8;
        float iv1 = inv[r1], bb1 = bet[r1];
        float iv2 = inv[r2], bb2 = bet[r2];
        #pragma unroll
        for (int ni = 0; ni < 8; ni++) {
            int nc = n0 + nw * 64 + ni * 8 + 2 * tig;
            #pragma unroll
            for (int q = 0; q < 2; q++) {
                int ncol = nc + q;
                if (ncol < NCOLS) {
                    float v1 = acc[mi][ni][q]     * iv1 + bb1;
                    float v2 = acc[mi][ni][2 + q] * iv2 + bb2;
                    v1 = v1 > 0.f ? v1 : 0.f;
                    v2 = v2 > 0.f ? v2 : 0.f;
                    size_t base = (size_t)ncol * NC;
                    splitstore(v1, &oh[base + r1], &ol[base + r1]);
                    splitstore(v2, &oh[base + r2], &ol[base + r2]);
                }
            }
        }
    }
}

__global__ __launch_bounds__(128, 2)
void conv1_k(const __half* xh, const __half* xl, const __half* wh, const __half* wl,
             const float* inv, const float* bet, __half* oh, __half* ol) {
    conv_cl_body<CIN1P, 3, 1, 0, T0, T1>(xh, xl, wh, wl, inv, bet, oh, ol);
}
__global__ __launch_bounds__(128, 2)
void conv2_k(const __half* xh, const __half* xl, const __half* wh, const __half* wl,
             const float* inv, const float* bet, __half* oh, __half* ol) {
    conv_cl_body<NC, 3, 1, 1, T1, T1>(xh, xl, wh, wl, inv, bet, oh, ol);
}
__global__ __launch_bounds__(128, 2)
void conv3_k(const __half* xh, const __half* xl, const __half* wh, const __half* wl,
             const float* inv, const float* bet, __half* oh, __half* ol) {
    conv_cl_body<NC, 4, 2, 1, T1, T2>(xh, xl, wh, wl, inv, bet, oh, ol);
}
__global__ __launch_bounds__(128, 2)
void conv45_k(const __half* xh, const __half* xl, const __half* wh, const __half* wl,
              const float* inv, const float* bet, __half* oh, __half* ol) {
    conv_cl_body<NC, 3, 1, 1, T2, T2>(xh, xl, wh, wl, inv, bet, oh, ol);
}

// ---------------- 1x1 projection + bias -> z [B, T', D] (channel-last input) ----------
__global__ __launch_bounds__(256)
void conv6_k(const __half* __restrict__ xh, const __half* __restrict__ xl,
             const float* __restrict__ w6, const float* __restrict__ b6,
             float* __restrict__ z)
{
    __shared__ float Xs[16][65];
    __shared__ float Ws[16][65];
    const int tx = threadIdx.x, ty = threadIdx.y;
    const int tid = ty * 16 + tx;
    const int t0 = blockIdx.x * 64;
    const int b  = blockIdx.y;

    float acc[4][4] = {};
    for (int c0 = 0; c0 < NC; c0 += 16) {
        #pragma unroll
        for (int j = 0; j < 4; j++) {
            int idx = tid + j * 256;
            int tl = idx >> 4, kk = idx & 15;
            int t = t0 + tl;
            float val = 0.f;
            if (t < T2) {
                size_t gi = ((size_t)b * T2 + t) * NC + c0 + kk;
                val = __half2float(xh[gi]) + __half2float(xl[gi]);
            }
            Xs[kk][tl] = val;
        }
        #pragma unroll
        for (int j = 0; j < 4; j++) {
            int idx = tid + j * 256;
            int dl = idx & 63, kk = idx >> 6;
            Ws[kk][dl] = w6[dl * NC + c0 + kk];
        }
        __syncthreads();
        #pragma unroll
        for (int k = 0; k < 16; k++) {
            float a[4], wv[4];
            #pragma unroll
            for (int i = 0; i < 4; i++) a[i] = Xs[k][ty * 4 + i];
            #pragma unroll
            for (int j = 0; j < 4; j++) wv[j] = Ws[k][tx * 4 + j];
            #pragma unroll
            for (int i = 0; i < 4; i++)
                #pragma unroll
                for (int j = 0; j < 4; j++)
                    acc[i][j] = fmaf(a[i], wv[j], acc[i][j]);
        }
        __syncthreads();
    }
    #pragma unroll
    for (int i = 0; i < 4; i++) {
        int t = t0 + ty * 4 + i;
        if (t < T2) {
            #pragma unroll
            for (int j = 0; j < 4; j++) {
                int d = tx * 4 + j;
                z[((size_t)b * T2 + t) * ND + d] = acc[i][j] + b6[d];
            }
        }
    }
}

// ---------------- VQ distance GEMM (fp32) ----------------
__global__ __launch_bounds__(256)
void dist_k(const float* __restrict__ emb)
{
    __shared__ float zs[64][65];
    __shared__ float es[64][65];
    const int tx = threadIdx.x, ty = threadIdx.y;
    const int tid = ty * 16 + tx;
    const int row0 = blockIdx.x * 64;
    const int e0   = blockIdx.y * 64;

    #pragma unroll
    for (int j = 0; j < 16; j++) {
        int idx = tid + j * 256;
        int k = idx & 63, r = idx >> 6;
        zs[r][k] = (row0 + r < NQ) ? g_z[(size_t)(row0 + r) * ND + k] : 0.f;
    }
    #pragma unroll
    for (int j = 0; j < 16; j++) {
        int idx = tid + j * 256;
        int k = idx & 63, e = idx >> 6;
        es[e][k] = emb[(size_t)(e0 + e) * ND + k];
    }
    __syncthreads();

    float acc[4][4] = {};
    #pragma unroll
    for (int k = 0; k < 64; k++) {
        float a[4], b[4];
        #pragma unroll
        for (int i = 0; i < 4; i++) a[i] = zs[ty * 4 + i][k];
        #pragma unroll
        for (int j = 0; j < 4; j++) b[j] = es[tx * 4 + j][k];
        #pragma unroll
        for (int i = 0; i < 4; i++)
            #pragma unroll
            for (int j = 0; j < 4; j++)
                acc[i][j] = fmaf(a[i], b[j], acc[i][j]);
    }

    #pragma unroll
    for (int i = 0; i < 4; i++) {
        int row = row0 + ty * 4 + i;
        if (row < NQ) {
            #pragma unroll
            for (int j = 0; j < 4; j++) {
                int e = e0 + tx * 4 + j;
                g_dist[(size_t)row * NM + e] = g_e2[e] - 2.f * acc[i][j];
            }
        }
    }
}

// ---------------- argmin + quantize + loss + counts ----------------
__global__ __launch_bounds__(256)
void vq_k(const float* __restrict__ emb, float* __restrict__ out_q)
{
    const int warp = threadIdx.x >> 5;
    const int lane = threadIdx.x & 31;
    const int row = blockIdx.x * 8 + warp;
    const float* dr = g_dist + (size_t)row * NM;

    float best = 3.4e38f; int bi = NM;
    #pragma unroll
    for (int i = 0; i < 16; i++) {
        int e = i * 32 + lane;
        float v = dr[e];
        if (v < best) { best = v; bi = e; }
    }
    #pragma unroll
    for (int off = 16; off > 0; off >>= 1) {
        float ob = __shfl_down_sync(0xffffffffu, best, off);
        int   oi = __shfl_down_sync(0xffffffffu, bi,   off);
        if (ob < best || (ob == best && oi < bi)) { best = ob; bi = oi; }
    }
    bi = __shfl_sync(0xffffffffu, bi, 0);

    const float* zr = g_z + (size_t)row * ND;
    const float* er = emb + (size_t)bi * ND;
    float lsum = 0.f;
    #pragma unroll
    for (int d0 = 0; d0 < ND; d0 += 32) {
        int d = d0 + lane;
        float zv = zr[d], qv = er[d];
        out_q[(size_t)row * ND + d] = zv + (qv - zv);
        float df = zv - qv;
        lsum += df * df;
    }
    #pragma unroll
    for (int off = 16; off > 0; off >>= 1)
        lsum += __shfl_down_sync(0xffffffffu, lsum, off);
    if (lane == 0) {
        atomicAdd(&g_loss[0], lsum);
        atomicAdd(&g_counts[bi], 1);
    }
}

__global__ void finalize_k(float* __restrict__ out)
{
    __shared__ float sh[NM];
    int tid = threadIdx.x;
    float p = (float)g_counts[tid] / (float)NQ;
    sh[tid] = -p * logf(p + 1e-10f);
    __syncthreads();
    for (int s = NM / 2; s > 0; s >>= 1) {
        if (tid < s) sh[tid] += sh[tid + s];
        __syncthreads();
    }
    if (tid == 0) {
        out[NQE]     = 0.25f * g_loss[0] / (float)NQE;
        out[NQE + 1] = expf(sh[0]);
    }
}

// ---------------- host-side driver ----------------
static void encoder_run(const float* mels, const float* w1, const float* w2,
                        const float* w3, const float* w4, const float* w5,
                        const float* w6, const float* b6,
                        const float* bng, const float* bnb,
                        const float* bnm, const float* bnv,
                        const float* emb, float* out)
{
    __half *mh, *ml, *pAh, *pAl, *pBh, *pBl;
    __half *w1h, *w1l, *w2h, *w2l, *w3h, *w3l, *w4h, *w4l, *w5h, *w5l;
    float *zbuf, *bnInv, *bnBeta;
    cudaGetSymbolAddress((void**)&mh, g_m_h);   cudaGetSymbolAddress((void**)&ml, g_m_l);
    cudaGetSymbolAddress((void**)&pAh, g_pA_h); cudaGetSymbolAddress((void**)&pAl, g_pA_l);
    cudaGetSymbolAddress((void**)&pBh, g_pB_h); cudaGetSymbolAddress((void**)&pBl, g_pB_l);
    cudaGetSymbolAddress((void**)&w1h, g_w1h);  cudaGetSymbolAddress((void**)&w1l, g_w1l);
    cudaGetSymbolAddress((void**)&w2h, g_w2h);  cudaGetSymbolAddress((void**)&w2l, g_w2l);
    cudaGetSymbolAddress((void**)&w3h, g_w3h);  cudaGetSymbolAddress((void**)&w3l, g_w3l);
    cudaGetSymbolAddress((void**)&w4h, g_w4h);  cudaGetSymbolAddress((void**)&w4l, g_w4l);
    cudaGetSymbolAddress((void**)&w5h, g_w5h);  cudaGetSymbolAddress((void**)&w5l, g_w5l);
    cudaGetSymbolAddress((void**)&zbuf, g_z);
    cudaGetSymbolAddress((void**)&bnInv,  g_bnInv);
    cudaGetSymbolAddress((void**)&bnBeta, g_bnBeta);

    cudaFuncSetAttribute(conv1_k,  cudaFuncAttributeMaxDynamicSharedMemorySize, SMEM2);
    cudaFuncSetAttribute(conv2_k,  cudaFuncAttributeMaxDynamicSharedMemorySize, SMEM2);
    cudaFuncSetAttribute(conv3_k,  cudaFuncAttributeMaxDynamicSharedMemorySize, SMEM2);
    cudaFuncSetAttribute(conv45_k, cudaFuncAttributeMaxDynamicSharedMemorySize, SMEM2);

    // launch 0: prep;  launch 1: pack;  launch 2: conv1;  launch 3: conv2 (ncu target)
    prep_k<<<(5 * NC + 255) / 256, 256>>>(bng, bnb, bnm, bnv, emb);
    packall_k<<<(PACKALL_N + 255) / 256, 256>>>(w1, w2, w3, w4, w5, mels);

    conv1_k<<<dim3((NB * T1 + 127) / 128, NC / 128), 128, SMEM2>>>(
        mh, ml, w1h, w1l, bnInv + 0 * NC, bnBeta + 0 * NC, pAh, pAl);
    conv2_k<<<dim3((NB * T1 + 127) / 128, NC / 128), 128, SMEM2>>>(
        pAh, pAl, w2h, w2l, bnInv + 1 * NC, bnBeta + 1 * NC, pBh, pBl);
    conv3_k<<<dim3((NB * T2 + 127) / 128, NC / 128), 128, SMEM2>>>(
        pBh, pBl, w3h, w3l, bnInv + 2 * NC, bnBeta + 2 * NC, pAh, pAl);
    conv45_k<<<dim3((NB * T2 + 127) / 128, NC / 128), 128, SMEM2>>>(
        pAh, pAl, w4h, w4l, bnInv + 3 * NC, bnBeta + 3 * NC, pBh, pBl);
    conv45_k<<<dim3((NB * T2 + 127) / 128, NC / 128), 128, SMEM2>>>(
        pBh, pBl, w5h, w5l, bnInv + 4 * NC, bnBeta + 4 * NC, pAh, pAl);
    conv6_k<<<dim3((T2 + 63) / 64, NB), dim3(16, 16)>>>(pAh, pAl, w6, b6, zbuf);
    dist_k<<<dim3((NQ + 63) / 64, NM / 64), dim3(16, 16)>>>(emb);
    vq_k<<<NQ / 8, 256>>>(emb, out);
    finalize_k<<<1, NM>>>(out);
}

extern "C" void kernel_launch(void* const* d_in, const int* in_sizes, int n_in,
                              void* d_out, int out_size)
{
    encoder_run((const float*)d_in[0], (const float*)d_in[1], (const float*)d_in[2],
                (const float*)d_in[3], (const float*)d_in[4], (const float*)d_in[5],
                (const float*)d_in[6], (const float*)d_in[7], (const float*)d_in[8],
                (const float*)d_in[9], (const float*)d_in[10], (const float*)d_in[11],
                (const float*)d_in[12], (float*)d_out);
}